// round 1
// baseline (speedup 1.0000x reference)
#include <cuda_runtime.h>
#include <math.h>

#define BB 2
#define SS 2048
#define DM 1024
#define NH 16
#define HD 64
#define MROWS (BB*SS)                      // 4096
#define Z_ELEMS ((size_t)BB*SS*DM)         // 4,194,304
#define HEAD_ELEMS ((size_t)BB*NH*SS*HD)   // 4,194,304

// scratch (static device arrays: allocation-free)
__device__ float g_Qh[BB*NH*SS*HD];
__device__ float g_Kh[BB*NH*SS*HD];
__device__ float g_Vh[BB*NH*SS*HD];
__device__ float g_Z[BB*SS*DM];

// ---------------------------------------------------------------------------
// Generic 128x128x16 tiled fp32 GEMM:  out = X @ W^T + bias
// X: [4096, 1024] row-major, W: [1024, 1024] row-major (row n = output feature)
// MODE 0/1/2: write to g_Qh/g_Kh/g_Vh in [B,H,S,Dh] layout
// MODE 3:     X = g_Z, write to outp in [B,S,D] layout
// ---------------------------------------------------------------------------
template<int MODE>
__global__ __launch_bounds__(256) void gemm_kernel(
    const float* __restrict__ Xin, const float* __restrict__ W,
    const float* __restrict__ bias, float* __restrict__ outp)
{
    const float* X = (MODE == 3) ? g_Z : Xin;
    float* out = (MODE == 0) ? g_Qh : (MODE == 1) ? g_Kh
               : (MODE == 2) ? g_Vh : outp;

    __shared__ float As[16][132];
    __shared__ float Bs[16][132];

    const int m0 = blockIdx.y * 128;
    const int n0 = blockIdx.x * 128;
    const int tid = threadIdx.x;
    const int rowBase = (tid >> 4) * 8;
    const int colBase = (tid & 15) * 8;

    float acc[8][8];
#pragma unroll
    for (int i = 0; i < 8; i++)
#pragma unroll
        for (int j = 0; j < 8; j++) acc[i][j] = 0.f;

    for (int k0 = 0; k0 < DM; k0 += 16) {
#pragma unroll
        for (int r = 0; r < 2; r++) {
            int f4 = tid + r * 256;           // 0..511
            int row = f4 >> 2;                // 0..127
            int kc = (f4 & 3) * 4;            // 0,4,8,12
            float4 a = *reinterpret_cast<const float4*>(
                X + (size_t)(m0 + row) * DM + k0 + kc);
            As[kc + 0][row] = a.x; As[kc + 1][row] = a.y;
            As[kc + 2][row] = a.z; As[kc + 3][row] = a.w;
            float4 b = *reinterpret_cast<const float4*>(
                W + (size_t)(n0 + row) * DM + k0 + kc);
            Bs[kc + 0][row] = b.x; Bs[kc + 1][row] = b.y;
            Bs[kc + 2][row] = b.z; Bs[kc + 3][row] = b.w;
        }
        __syncthreads();
#pragma unroll
        for (int k = 0; k < 16; k++) {
            float a[8], b[8];
#pragma unroll
            for (int i = 0; i < 8; i++) a[i] = As[k][rowBase + i];
#pragma unroll
            for (int j = 0; j < 8; j++) b[j] = Bs[k][colBase + j];
#pragma unroll
            for (int i = 0; i < 8; i++)
#pragma unroll
                for (int j = 0; j < 8; j++) acc[i][j] = fmaf(a[i], b[j], acc[i][j]);
        }
        __syncthreads();
    }

#pragma unroll
    for (int i = 0; i < 8; i++) {
        int m = m0 + rowBase + i;
        int bidx = m >> 11;        // m / 2048
        int s = m & (SS - 1);
#pragma unroll
        for (int j = 0; j < 8; j++) {
            int n = n0 + colBase + j;
            float v = acc[i][j] + bias[n];
            if (MODE <= 2) {
                // [B,H,S,Dh]
                out[(((size_t)bidx * NH + (n >> 6)) * SS + s) * HD + (n & 63)] = v;
            } else {
                out[(size_t)m * DM + n] = v;
            }
        }
    }
}

// ---------------------------------------------------------------------------
// scores: per (b,h)  C[2048,2048] = Q[2048,64] @ K^T[64,2048] * 0.125
// 64x64 tiles, BK=16
// ---------------------------------------------------------------------------
__global__ __launch_bounds__(256) void scores_kernel(float* __restrict__ attn)
{
    __shared__ float Qs[16][68];
    __shared__ float Ks[16][68];

    const int bh = blockIdx.z;
    const float* Q = g_Qh + (size_t)bh * SS * HD;
    const float* K = g_Kh + (size_t)bh * SS * HD;
    float* C = attn + (size_t)bh * SS * SS;

    const int m0 = blockIdx.y * 64;
    const int n0 = blockIdx.x * 64;
    const int tid = threadIdx.x;
    const int rowBase = (tid >> 4) * 4;
    const int colBase = (tid & 15) * 4;

    float acc[4][4];
#pragma unroll
    for (int i = 0; i < 4; i++)
#pragma unroll
        for (int j = 0; j < 4; j++) acc[i][j] = 0.f;

    const int lrow = tid >> 2;          // 0..63
    const int lkc = (tid & 3) * 4;      // 0,4,8,12

#pragma unroll
    for (int k0 = 0; k0 < HD; k0 += 16) {
        float4 qv = *reinterpret_cast<const float4*>(
            Q + (size_t)(m0 + lrow) * HD + k0 + lkc);
        Qs[lkc + 0][lrow] = qv.x; Qs[lkc + 1][lrow] = qv.y;
        Qs[lkc + 2][lrow] = qv.z; Qs[lkc + 3][lrow] = qv.w;
        float4 kv = *reinterpret_cast<const float4*>(
            K + (size_t)(n0 + lrow) * HD + k0 + lkc);
        Ks[lkc + 0][lrow] = kv.x; Ks[lkc + 1][lrow] = kv.y;
        Ks[lkc + 2][lrow] = kv.z; Ks[lkc + 3][lrow] = kv.w;
        __syncthreads();
#pragma unroll
        for (int k = 0; k < 16; k++) {
            float a[4], b[4];
#pragma unroll
            for (int i = 0; i < 4; i++) a[i] = Qs[k][rowBase + i];
#pragma unroll
            for (int j = 0; j < 4; j++) b[j] = Ks[k][colBase + j];
#pragma unroll
            for (int i = 0; i < 4; i++)
#pragma unroll
                for (int j = 0; j < 4; j++) acc[i][j] = fmaf(a[i], b[j], acc[i][j]);
        }
        __syncthreads();
    }

    const float scale = 0.125f;   // 1/sqrt(64)
#pragma unroll
    for (int i = 0; i < 4; i++) {
        int m = m0 + rowBase + i;
        float4 o = make_float4(acc[i][0] * scale, acc[i][1] * scale,
                               acc[i][2] * scale, acc[i][3] * scale);
        *reinterpret_cast<float4*>(C + (size_t)m * SS + n0 + colBase) = o;
    }
}

// ---------------------------------------------------------------------------
// softmax: in-place over last dim (2048), one block per row, 256 threads
// ---------------------------------------------------------------------------
__global__ __launch_bounds__(256) void softmax_kernel(float* __restrict__ attn)
{
    const size_t row = blockIdx.x;
    float4* p4 = reinterpret_cast<float4*>(attn + row * SS);
    const int tid = threadIdx.x;

    float4 v0 = p4[tid];
    float4 v1 = p4[tid + 256];

    float mx = fmaxf(fmaxf(fmaxf(v0.x, v0.y), fmaxf(v0.z, v0.w)),
                     fmaxf(fmaxf(v1.x, v1.y), fmaxf(v1.z, v1.w)));

    __shared__ float redm[8];
    __shared__ float reds[8];
    const int lane = tid & 31, wrp = tid >> 5;

#pragma unroll
    for (int o = 16; o > 0; o >>= 1)
        mx = fmaxf(mx, __shfl_xor_sync(0xffffffffu, mx, o));
    if (lane == 0) redm[wrp] = mx;
    __syncthreads();
    mx = redm[0];
#pragma unroll
    for (int w = 1; w < 8; w++) mx = fmaxf(mx, redm[w]);

    float4 e0, e1;
    e0.x = __expf(v0.x - mx); e0.y = __expf(v0.y - mx);
    e0.z = __expf(v0.z - mx); e0.w = __expf(v0.w - mx);
    e1.x = __expf(v1.x - mx); e1.y = __expf(v1.y - mx);
    e1.z = __expf(v1.z - mx); e1.w = __expf(v1.w - mx);

    float sm = (e0.x + e0.y + e0.z + e0.w) + (e1.x + e1.y + e1.z + e1.w);
#pragma unroll
    for (int o = 16; o > 0; o >>= 1)
        sm += __shfl_xor_sync(0xffffffffu, sm, o);
    if (lane == 0) reds[wrp] = sm;
    __syncthreads();
    sm = reds[0];
#pragma unroll
    for (int w = 1; w < 8; w++) sm += reds[w];

    const float inv = 1.0f / sm;
    e0.x *= inv; e0.y *= inv; e0.z *= inv; e0.w *= inv;
    e1.x *= inv; e1.y *= inv; e1.z *= inv; e1.w *= inv;
    p4[tid] = e0;
    p4[tid + 256] = e1;
}

// ---------------------------------------------------------------------------
// AV: per (b,h)  Z[2048,64] = P[2048,2048] @ V[2048,64], written to [B,S,D]
// 128-row tiles, full 64 cols per block, BK=32
// ---------------------------------------------------------------------------
__global__ __launch_bounds__(256) void av_kernel(const float* __restrict__ attn)
{
    __shared__ float Ps[32][132];
    __shared__ float Vs[32][68];

    const int bh = blockIdx.z;
    const int b = bh >> 4, h = bh & 15;
    const float* P = attn + (size_t)bh * SS * SS;
    const float* V = g_Vh + (size_t)bh * SS * HD;

    const int m0 = blockIdx.x * 128;
    const int tid = threadIdx.x;
    const int rowBase = (tid >> 4) * 8;
    const int colBase = (tid & 15) * 4;

    float acc[8][4];
#pragma unroll
    for (int i = 0; i < 8; i++)
#pragma unroll
        for (int j = 0; j < 4; j++) acc[i][j] = 0.f;

    for (int k0 = 0; k0 < SS; k0 += 32) {
#pragma unroll
        for (int r = 0; r < 4; r++) {
            int f4 = tid + r * 256;       // 0..1023
            int row = f4 >> 3;            // 0..127
            int kc = (f4 & 7) * 4;        // 0..28
            float4 pv = *reinterpret_cast<const float4*>(
                P + (size_t)(m0 + row) * SS + k0 + kc);
            Ps[kc + 0][row] = pv.x; Ps[kc + 1][row] = pv.y;
            Ps[kc + 2][row] = pv.z; Ps[kc + 3][row] = pv.w;
        }
#pragma unroll
        for (int r = 0; r < 2; r++) {
            int f4 = tid + r * 256;       // 0..511
            int krow = f4 >> 4;           // 0..31
            int nc = (f4 & 15) * 4;       // 0..60
            float4 vv = *reinterpret_cast<const float4*>(
                V + (size_t)(k0 + krow) * HD + nc);
            *reinterpret_cast<float4*>(&Vs[krow][nc]) = vv;
        }
        __syncthreads();
#pragma unroll
        for (int k = 0; k < 32; k++) {
            float4 bv = *reinterpret_cast<float4*>(&Vs[k][colBase]);
            float a[8];
#pragma unroll
            for (int i = 0; i < 8; i++) a[i] = Ps[k][rowBase + i];
#pragma unroll
            for (int i = 0; i < 8; i++) {
                acc[i][0] = fmaf(a[i], bv.x, acc[i][0]);
                acc[i][1] = fmaf(a[i], bv.y, acc[i][1]);
                acc[i][2] = fmaf(a[i], bv.z, acc[i][2]);
                acc[i][3] = fmaf(a[i], bv.w, acc[i][3]);
            }
        }
        __syncthreads();
    }

#pragma unroll
    for (int i = 0; i < 8; i++) {
        int m = m0 + rowBase + i;
        float4 o = make_float4(acc[i][0], acc[i][1], acc[i][2], acc[i][3]);
        *reinterpret_cast<float4*>(
            &g_Z[((size_t)b * SS + m) * DM + h * HD + colBase]) = o;
    }
}

// ---------------------------------------------------------------------------
extern "C" void kernel_launch(void* const* d_in, const int* in_sizes, int n_in,
                              void* d_out, int out_size)
{
    const float* q   = (const float*)d_in[0];
    const float* k   = (const float*)d_in[1];
    const float* v   = (const float*)d_in[2];
    const float* w_q = (const float*)d_in[3];
    const float* b_q = (const float*)d_in[4];
    const float* w_k = (const float*)d_in[5];
    const float* b_k = (const float*)d_in[6];
    const float* w_v = (const float*)d_in[7];
    const float* b_v = (const float*)d_in[8];
    const float* w_o = (const float*)d_in[9];
    const float* b_o = (const float*)d_in[10];

    float* out = (float*)d_out;
    float* z_out = out;                    // [B,S,D]
    float* attn_out = out + Z_ELEMS;       // [B,H,S,S]

    dim3 gp(DM / 128, MROWS / 128);        // (8, 32)
    gemm_kernel<0><<<gp, 256>>>(q, w_q, b_q, nullptr);
    gemm_kernel<1><<<gp, 256>>>(k, w_k, b_k, nullptr);
    gemm_kernel<2><<<gp, 256>>>(v, w_v, b_v, nullptr);

    scores_kernel<<<dim3(SS / 64, SS / 64, BB * NH), 256>>>(attn_out);
    softmax_kernel<<<BB * NH * SS, 256>>>(attn_out);
    av_kernel<<<dim3(SS / 128, 1, BB * NH), 256>>>(attn_out);

    gemm_kernel<3><<<gp, 256>>>(nullptr, w_o, b_o, z_out);
}

// round 2
// speedup vs baseline: 1.0002x; 1.0002x over previous
#include <cuda_runtime.h>
#include <math.h>

#define BB 2
#define SS 2048
#define DM 1024
#define NH 16
#define HD 64
#define MROWS (BB*SS)                      // 4096
#define Z_ELEMS ((size_t)BB*SS*DM)         // 4,194,304
#define HEAD_ELEMS ((size_t)BB*NH*SS*HD)   // 4,194,304

// scratch (static device arrays: allocation-free)
__device__ float g_Qh[BB*NH*SS*HD];
__device__ float g_Kh[BB*NH*SS*HD];
__device__ float g_Vh[BB*NH*SS*HD];
__device__ float g_Z[BB*SS*DM];

// ---------------------------------------------------------------------------
// Generic 128x128x16 tiled fp32 GEMM:  out = X @ W^T + bias
// X: [4096, 1024] row-major, W: [1024, 1024] row-major (row n = output feature)
// MODE 0/1/2: write to g_Qh/g_Kh/g_Vh in [B,H,S,Dh] layout
// MODE 3:     X = g_Z, write to outp in [B,S,D] layout
// ---------------------------------------------------------------------------
template<int MODE>
__global__ __launch_bounds__(256) void gemm_kernel(
    const float* __restrict__ Xin, const float* __restrict__ W,
    const float* __restrict__ bias, float* __restrict__ outp)
{
    const float* X = (MODE == 3) ? g_Z : Xin;
    float* out = (MODE == 0) ? g_Qh : (MODE == 1) ? g_Kh
               : (MODE == 2) ? g_Vh : outp;

    __shared__ float As[16][132];
    __shared__ float Bs[16][132];

    const int m0 = blockIdx.y * 128;
    const int n0 = blockIdx.x * 128;
    const int tid = threadIdx.x;
    const int rowBase = (tid >> 4) * 8;
    const int colBase = (tid & 15) * 8;

    float acc[8][8];
#pragma unroll
    for (int i = 0; i < 8; i++)
#pragma unroll
        for (int j = 0; j < 8; j++) acc[i][j] = 0.f;

    for (int k0 = 0; k0 < DM; k0 += 16) {
#pragma unroll
        for (int r = 0; r < 2; r++) {
            int f4 = tid + r * 256;           // 0..511
            int row = f4 >> 2;                // 0..127
            int kc = (f4 & 3) * 4;            // 0,4,8,12
            float4 a = *reinterpret_cast<const float4*>(
                X + (size_t)(m0 + row) * DM + k0 + kc);
            As[kc + 0][row] = a.x; As[kc + 1][row] = a.y;
            As[kc + 2][row] = a.z; As[kc + 3][row] = a.w;
            float4 b = *reinterpret_cast<const float4*>(
                W + (size_t)(n0 + row) * DM + k0 + kc);
            Bs[kc + 0][row] = b.x; Bs[kc + 1][row] = b.y;
            Bs[kc + 2][row] = b.z; Bs[kc + 3][row] = b.w;
        }
        __syncthreads();
#pragma unroll
        for (int k = 0; k < 16; k++) {
            float a[8], b[8];
#pragma unroll
            for (int i = 0; i < 8; i++) a[i] = As[k][rowBase + i];
#pragma unroll
            for (int j = 0; j < 8; j++) b[j] = Bs[k][colBase + j];
#pragma unroll
            for (int i = 0; i < 8; i++)
#pragma unroll
                for (int j = 0; j < 8; j++) acc[i][j] = fmaf(a[i], b[j], acc[i][j]);
        }
        __syncthreads();
    }

#pragma unroll
    for (int i = 0; i < 8; i++) {
        int m = m0 + rowBase + i;
        int bidx = m >> 11;        // m / 2048
        int s = m & (SS - 1);
#pragma unroll
        for (int j = 0; j < 8; j++) {
            int n = n0 + colBase + j;
            float v = acc[i][j] + bias[n];
            if (MODE <= 2) {
                // [B,H,S,Dh]
                out[(((size_t)bidx * NH + (n >> 6)) * SS + s) * HD + (n & 63)] = v;
            } else {
                out[(size_t)m * DM + n] = v;
            }
        }
    }
}

// ---------------------------------------------------------------------------
// scores: per (b,h)  C[2048,2048] = Q[2048,64] @ K^T[64,2048] * 0.125
// 64x64 tiles, BK=16
// ---------------------------------------------------------------------------
__global__ __launch_bounds__(256) void scores_kernel(float* __restrict__ attn)
{
    __shared__ float Qs[16][68];
    __shared__ float Ks[16][68];

    const int bh = blockIdx.z;
    const float* Q = g_Qh + (size_t)bh * SS * HD;
    const float* K = g_Kh + (size_t)bh * SS * HD;
    float* C = attn + (size_t)bh * SS * SS;

    const int m0 = blockIdx.y * 64;
    const int n0 = blockIdx.x * 64;
    const int tid = threadIdx.x;
    const int rowBase = (tid >> 4) * 4;
    const int colBase = (tid & 15) * 4;

    float acc[4][4];
#pragma unroll
    for (int i = 0; i < 4; i++)
#pragma unroll
        for (int j = 0; j < 4; j++) acc[i][j] = 0.f;

    const int lrow = tid >> 2;          // 0..63
    const int lkc = (tid & 3) * 4;      // 0,4,8,12

#pragma unroll
    for (int k0 = 0; k0 < HD; k0 += 16) {
        float4 qv = *reinterpret_cast<const float4*>(
            Q + (size_t)(m0 + lrow) * HD + k0 + lkc);
        Qs[lkc + 0][lrow] = qv.x; Qs[lkc + 1][lrow] = qv.y;
        Qs[lkc + 2][lrow] = qv.z; Qs[lkc + 3][lrow] = qv.w;
        float4 kv = *reinterpret_cast<const float4*>(
            K + (size_t)(n0 + lrow) * HD + k0 + lkc);
        Ks[lkc + 0][lrow] = kv.x; Ks[lkc + 1][lrow] = kv.y;
        Ks[lkc + 2][lrow] = kv.z; Ks[lkc + 3][lrow] = kv.w;
        __syncthreads();
#pragma unroll
        for (int k = 0; k < 16; k++) {
            float a[4], b[4];
#pragma unroll
            for (int i = 0; i < 4; i++) a[i] = Qs[k][rowBase + i];
#pragma unroll
            for (int j = 0; j < 4; j++) b[j] = Ks[k][colBase + j];
#pragma unroll
            for (int i = 0; i < 4; i++)
#pragma unroll
                for (int j = 0; j < 4; j++) acc[i][j] = fmaf(a[i], b[j], acc[i][j]);
        }
        __syncthreads();
    }

    const float scale = 0.125f;   // 1/sqrt(64)
#pragma unroll
    for (int i = 0; i < 4; i++) {
        int m = m0 + rowBase + i;
        float4 o = make_float4(acc[i][0] * scale, acc[i][1] * scale,
                               acc[i][2] * scale, acc[i][3] * scale);
        *reinterpret_cast<float4*>(C + (size_t)m * SS + n0 + colBase) = o;
    }
}

// ---------------------------------------------------------------------------
// softmax: in-place over last dim (2048), one block per row, 256 threads
// ---------------------------------------------------------------------------
__global__ __launch_bounds__(256) void softmax_kernel(float* __restrict__ attn)
{
    const size_t row = blockIdx.x;
    float4* p4 = reinterpret_cast<float4*>(attn + row * SS);
    const int tid = threadIdx.x;

    float4 v0 = p4[tid];
    float4 v1 = p4[tid + 256];

    float mx = fmaxf(fmaxf(fmaxf(v0.x, v0.y), fmaxf(v0.z, v0.w)),
                     fmaxf(fmaxf(v1.x, v1.y), fmaxf(v1.z, v1.w)));

    __shared__ float redm[8];
    __shared__ float reds[8];
    const int lane = tid & 31, wrp = tid >> 5;

#pragma unroll
    for (int o = 16; o > 0; o >>= 1)
        mx = fmaxf(mx, __shfl_xor_sync(0xffffffffu, mx, o));
    if (lane == 0) redm[wrp] = mx;
    __syncthreads();
    mx = redm[0];
#pragma unroll
    for (int w = 1; w < 8; w++) mx = fmaxf(mx, redm[w]);

    float4 e0, e1;
    e0.x = __expf(v0.x - mx); e0.y = __expf(v0.y - mx);
    e0.z = __expf(v0.z - mx); e0.w = __expf(v0.w - mx);
    e1.x = __expf(v1.x - mx); e1.y = __expf(v1.y - mx);
    e1.z = __expf(v1.z - mx); e1.w = __expf(v1.w - mx);

    float sm = (e0.x + e0.y + e0.z + e0.w) + (e1.x + e1.y + e1.z + e1.w);
#pragma unroll
    for (int o = 16; o > 0; o >>= 1)
        sm += __shfl_xor_sync(0xffffffffu, sm, o);
    if (lane == 0) reds[wrp] = sm;
    __syncthreads();
    sm = reds[0];
#pragma unroll
    for (int w = 1; w < 8; w++) sm += reds[w];

    const float inv = 1.0f / sm;
    e0.x *= inv; e0.y *= inv; e0.z *= inv; e0.w *= inv;
    e1.x *= inv; e1.y *= inv; e1.z *= inv; e1.w *= inv;
    p4[tid] = e0;
    p4[tid + 256] = e1;
}

// ---------------------------------------------------------------------------
// AV: per (b,h)  Z[2048,64] = P[2048,2048] @ V[2048,64], written to [B,S,D]
// 128-row tiles, full 64 cols per block, BK=32
// ---------------------------------------------------------------------------
__global__ __launch_bounds__(256) void av_kernel(const float* __restrict__ attn)
{
    __shared__ float Ps[32][132];
    __shared__ float Vs[32][68];

    const int bh = blockIdx.z;
    const int b = bh >> 4, h = bh & 15;
    const float* P = attn + (size_t)bh * SS * SS;
    const float* V = g_Vh + (size_t)bh * SS * HD;

    const int m0 = blockIdx.x * 128;
    const int tid = threadIdx.x;
    const int rowBase = (tid >> 4) * 8;
    const int colBase = (tid & 15) * 4;

    float acc[8][4];
#pragma unroll
    for (int i = 0; i < 8; i++)
#pragma unroll
        for (int j = 0; j < 4; j++) acc[i][j] = 0.f;

    for (int k0 = 0; k0 < SS; k0 += 32) {
#pragma unroll
        for (int r = 0; r < 4; r++) {
            int f4 = tid + r * 256;       // 0..1023
            int row = f4 >> 3;            // 0..127
            int kc = (f4 & 7) * 4;        // 0..28
            float4 pv = *reinterpret_cast<const float4*>(
                P + (size_t)(m0 + row) * SS + k0 + kc);
            Ps[kc + 0][row] = pv.x; Ps[kc + 1][row] = pv.y;
            Ps[kc + 2][row] = pv.z; Ps[kc + 3][row] = pv.w;
        }
#pragma unroll
        for (int r = 0; r < 2; r++) {
            int f4 = tid + r * 256;       // 0..511
            int krow = f4 >> 4;           // 0..31
            int nc = (f4 & 15) * 4;       // 0..60
            float4 vv = *reinterpret_cast<const float4*>(
                V + (size_t)(k0 + krow) * HD + nc);
            *reinterpret_cast<float4*>(&Vs[krow][nc]) = vv;
        }
        __syncthreads();
#pragma unroll
        for (int k = 0; k < 32; k++) {
            float4 bv = *reinterpret_cast<float4*>(&Vs[k][colBase]);
            float a[8];
#pragma unroll
            for (int i = 0; i < 8; i++) a[i] = Ps[k][rowBase + i];
#pragma unroll
            for (int i = 0; i < 8; i++) {
                acc[i][0] = fmaf(a[i], bv.x, acc[i][0]);
                acc[i][1] = fmaf(a[i], bv.y, acc[i][1]);
                acc[i][2] = fmaf(a[i], bv.z, acc[i][2]);
                acc[i][3] = fmaf(a[i], bv.w, acc[i][3]);
            }
        }
        __syncthreads();
    }

#pragma unroll
    for (int i = 0; i < 8; i++) {
        int m = m0 + rowBase + i;
        float4 o = make_float4(acc[i][0], acc[i][1], acc[i][2], acc[i][3]);
        *reinterpret_cast<float4*>(
            &g_Z[((size_t)b * SS + m) * DM + h * HD + colBase]) = o;
    }
}

// ---------------------------------------------------------------------------
extern "C" void kernel_launch(void* const* d_in, const int* in_sizes, int n_in,
                              void* d_out, int out_size)
{
    const float* q   = (const float*)d_in[0];
    const float* k   = (const float*)d_in[1];
    const float* v   = (const float*)d_in[2];
    const float* w_q = (const float*)d_in[3];
    const float* b_q = (const float*)d_in[4];
    const float* w_k = (const float*)d_in[5];
    const float* b_k = (const float*)d_in[6];
    const float* w_v = (const float*)d_in[7];
    const float* b_v = (const float*)d_in[8];
    const float* w_o = (const float*)d_in[9];
    const float* b_o = (const float*)d_in[10];

    float* out = (float*)d_out;
    float* z_out = out;                    // [B,S,D]
    float* attn_out = out + Z_ELEMS;       // [B,H,S,S]

    dim3 gp(DM / 128, MROWS / 128);        // (8, 32)
    gemm_kernel<0><<<gp, 256>>>(q, w_q, b_q, nullptr);
    gemm_kernel<1><<<gp, 256>>>(k, w_k, b_k, nullptr);
    gemm_kernel<2><<<gp, 256>>>(v, w_v, b_v, nullptr);

    scores_kernel<<<dim3(SS / 64, SS / 64, BB * NH), 256>>>(attn_out);
    softmax_kernel<<<BB * NH * SS, 256>>>(attn_out);
    av_kernel<<<dim3(SS / 128, 1, BB * NH), 256>>>(attn_out);

    gemm_kernel<3><<<gp, 256>>>(nullptr, w_o, b_o, z_out);
}

// round 3
// speedup vs baseline: 1.9474x; 1.9470x over previous
#include <cuda_runtime.h>
#include <cuda_bf16.h>
#include <math.h>

#define BB 2
#define SS 2048
#define DM 1024
#define NH 16
#define HD 64
#define MROWS (BB*SS)                      // 4096
#define Z_ELEMS ((size_t)BB*SS*DM)         // 4,194,304

// scratch (static device arrays: allocation-free)
__device__ float g_Qh[BB*NH*SS*HD];
__device__ float g_Kh[BB*NH*SS*HD];
__device__ float g_Vh[BB*NH*SS*HD];
__device__ float g_Z[BB*SS*DM];

// ---------------------------------------------------------------------------
// helpers
// ---------------------------------------------------------------------------
__device__ __forceinline__ unsigned smem_u32(const void* p) {
    return (unsigned)__cvta_generic_to_shared(p);
}

__device__ __forceinline__ void ldm_x4(unsigned addr, unsigned& r0, unsigned& r1,
                                       unsigned& r2, unsigned& r3) {
    asm volatile("ldmatrix.sync.aligned.m8n8.x4.shared.b16 {%0,%1,%2,%3}, [%4];"
                 : "=r"(r0), "=r"(r1), "=r"(r2), "=r"(r3) : "r"(addr));
}
__device__ __forceinline__ void ldm_x2(unsigned addr, unsigned& r0, unsigned& r1) {
    asm volatile("ldmatrix.sync.aligned.m8n8.x2.shared.b16 {%0,%1}, [%2];"
                 : "=r"(r0), "=r"(r1) : "r"(addr));
}
__device__ __forceinline__ void mma16816(float* c, const unsigned* a, const unsigned* b) {
    asm volatile("mma.sync.aligned.m16n8k16.row.col.f32.bf16.bf16.f32 "
                 "{%0,%1,%2,%3}, {%4,%5,%6,%7}, {%8,%9}, {%0,%1,%2,%3};"
                 : "+f"(c[0]), "+f"(c[1]), "+f"(c[2]), "+f"(c[3])
                 : "r"(a[0]), "r"(a[1]), "r"(a[2]), "r"(a[3]), "r"(b[0]), "r"(b[1]));
}

__device__ __forceinline__ void split2(float x, __nv_bfloat16& h, __nv_bfloat16& l) {
    h = __float2bfloat16(x);
    l = __float2bfloat16(x - __bfloat162float(h));
}

// store float4 as hi/lo bf16x2 pairs into row [kc..kc+3]
__device__ __forceinline__ void split_store4(__nv_bfloat16* hrow, __nv_bfloat16* lrow,
                                             int kc, float4 v) {
    __nv_bfloat16 h0, h1, h2, h3, l0, l1, l2, l3;
    split2(v.x, h0, l0); split2(v.y, h1, l1);
    split2(v.z, h2, l2); split2(v.w, h3, l3);
    __nv_bfloat162 ph0; ph0.x = h0; ph0.y = h1;
    __nv_bfloat162 ph1; ph1.x = h2; ph1.y = h3;
    __nv_bfloat162 pl0; pl0.x = l0; pl0.y = l1;
    __nv_bfloat162 pl1; pl1.x = l2; pl1.y = l3;
    *reinterpret_cast<__nv_bfloat162*>(hrow + kc)     = ph0;
    *reinterpret_cast<__nv_bfloat162*>(hrow + kc + 2) = ph1;
    *reinterpret_cast<__nv_bfloat162*>(lrow + kc)     = pl0;
    *reinterpret_cast<__nv_bfloat162*>(lrow + kc + 2) = pl1;
}

// ---------------------------------------------------------------------------
// Projection GEMM (tensor cores): out = X @ W^T + bias
// X: [4096,1024], W: [1024,1024] row-major. Block tile 128x128, K-tile 32.
// 8 warps, warp tile 64x32 (mt 4 x nt 4 of m16n8).
// MODE 0/1/2: write [B,H,S,Dh] to g_Qh/g_Kh/g_Vh. MODE 3: X=g_Z, write [B,S,D].
// ---------------------------------------------------------------------------
template<int MODE>
__global__ __launch_bounds__(256) void proj_kernel(
    const float* __restrict__ Xin, const float* __restrict__ W,
    const float* __restrict__ bias, float* __restrict__ outp)
{
    const float* X = (MODE == 3) ? g_Z : Xin;
    float* out = (MODE == 0) ? g_Qh : (MODE == 1) ? g_Kh
               : (MODE == 2) ? g_Vh : outp;

    __shared__ alignas(16) __nv_bfloat16 Ah[128][40];
    __shared__ alignas(16) __nv_bfloat16 Al[128][40];
    __shared__ alignas(16) __nv_bfloat16 Bh[128][40];
    __shared__ alignas(16) __nv_bfloat16 Bl[128][40];

    const int m0 = blockIdx.y * 128;
    const int n0 = blockIdx.x * 128;
    const int tid = threadIdx.x;
    const int lane = tid & 31;
    const int w = tid >> 5;
    const int wm = (w >> 2) * 64;   // 0 or 64
    const int wn = (w & 3) * 32;    // 0,32,64,96

    float acc[4][4][4];
#pragma unroll
    for (int i = 0; i < 4; i++)
#pragma unroll
        for (int j = 0; j < 4; j++)
#pragma unroll
            for (int c = 0; c < 4; c++) acc[i][j][c] = 0.f;

    for (int k0 = 0; k0 < DM; k0 += 32) {
        // fill smem (A and B tiles, 128x32 each)
#pragma unroll
        for (int r = 0; r < 4; r++) {
            int idx = tid + r * 256;          // 0..1023
            int row = idx >> 3;               // 0..127
            int kc = (idx & 7) * 4;           // 0..28
            float4 a = *reinterpret_cast<const float4*>(
                X + (size_t)(m0 + row) * DM + k0 + kc);
            split_store4(&Ah[row][0], &Al[row][0], kc, a);
            float4 b = *reinterpret_cast<const float4*>(
                W + (size_t)(n0 + row) * DM + k0 + kc);
            split_store4(&Bh[row][0], &Bl[row][0], kc, b);
        }
        __syncthreads();

#pragma unroll
        for (int ks = 0; ks < 32; ks += 16) {
            unsigned ah[4][4], al[4][4], bh[4][2], bl[4][2];
            const int arow = wm + (lane & 15);
            const int acol = ks + (lane >> 4) * 8;
#pragma unroll
            for (int mt = 0; mt < 4; mt++) {
                ldm_x4(smem_u32(&Ah[arow + mt * 16][acol]),
                       ah[mt][0], ah[mt][1], ah[mt][2], ah[mt][3]);
                ldm_x4(smem_u32(&Al[arow + mt * 16][acol]),
                       al[mt][0], al[mt][1], al[mt][2], al[mt][3]);
            }
            const int brow = wn + (lane & 7);
            const int bcol = ks + ((lane >> 3) & 1) * 8;
#pragma unroll
            for (int nt = 0; nt < 4; nt++) {
                ldm_x2(smem_u32(&Bh[brow + nt * 8][bcol]), bh[nt][0], bh[nt][1]);
                ldm_x2(smem_u32(&Bl[brow + nt * 8][bcol]), bl[nt][0], bl[nt][1]);
            }
#pragma unroll
            for (int mt = 0; mt < 4; mt++)
#pragma unroll
                for (int nt = 0; nt < 4; nt++) {
                    mma16816(acc[mt][nt], ah[mt], bh[nt]);
                    mma16816(acc[mt][nt], ah[mt], bl[nt]);
                    mma16816(acc[mt][nt], al[mt], bh[nt]);
                }
        }
        __syncthreads();
    }

    // epilogue
#pragma unroll
    for (int mt = 0; mt < 4; mt++) {
        int mrow = m0 + wm + mt * 16 + (lane >> 2);
#pragma unroll
        for (int nt = 0; nt < 4; nt++) {
            int ncol = n0 + wn + nt * 8 + (lane & 3) * 2;
            float bx = bias[ncol], by = bias[ncol + 1];
#pragma unroll
            for (int half = 0; half < 2; half++) {
                int m = mrow + half * 8;
                float2 v;
                v.x = acc[mt][nt][half * 2 + 0] + bx;
                v.y = acc[mt][nt][half * 2 + 1] + by;
                if (MODE <= 2) {
                    int bidx = m >> 11;
                    int s = m & (SS - 1);
                    size_t off = (((size_t)bidx * NH + (ncol >> 6)) * SS + s) * HD
                               + (ncol & 63);
                    *reinterpret_cast<float2*>(out + off) = v;
                } else {
                    *reinterpret_cast<float2*>(out + (size_t)m * DM + ncol) = v;
                }
            }
        }
    }
}

// ---------------------------------------------------------------------------
// scores (tensor cores): per (b,h) C[2048,2048] = Q @ K^T * 0.125
// Block tile 128x128, K = 64 (two K-tiles of 32). Same warp layout as proj.
// ---------------------------------------------------------------------------
__global__ __launch_bounds__(256) void scores_kernel(float* __restrict__ attn)
{
    __shared__ alignas(16) __nv_bfloat16 Ah[128][40];
    __shared__ alignas(16) __nv_bfloat16 Al[128][40];
    __shared__ alignas(16) __nv_bfloat16 Bh[128][40];
    __shared__ alignas(16) __nv_bfloat16 Bl[128][40];

    const int bh = blockIdx.z;
    const float* Q = g_Qh + (size_t)bh * SS * HD;
    const float* K = g_Kh + (size_t)bh * SS * HD;
    float* C = attn + (size_t)bh * SS * SS;

    const int m0 = blockIdx.y * 128;
    const int n0 = blockIdx.x * 128;
    const int tid = threadIdx.x;
    const int lane = tid & 31;
    const int w = tid >> 5;
    const int wm = (w >> 2) * 64;
    const int wn = (w & 3) * 32;

    float acc[4][4][4];
#pragma unroll
    for (int i = 0; i < 4; i++)
#pragma unroll
        for (int j = 0; j < 4; j++)
#pragma unroll
            for (int c = 0; c < 4; c++) acc[i][j][c] = 0.f;

#pragma unroll
    for (int k0 = 0; k0 < HD; k0 += 32) {
#pragma unroll
        for (int r = 0; r < 4; r++) {
            int idx = tid + r * 256;
            int row = idx >> 3;
            int kc = (idx & 7) * 4;
            float4 a = *reinterpret_cast<const float4*>(
                Q + (size_t)(m0 + row) * HD + k0 + kc);
            split_store4(&Ah[row][0], &Al[row][0], kc, a);
            float4 b = *reinterpret_cast<const float4*>(
                K + (size_t)(n0 + row) * HD + k0 + kc);
            split_store4(&Bh[row][0], &Bl[row][0], kc, b);
        }
        __syncthreads();

#pragma unroll
        for (int ks = 0; ks < 32; ks += 16) {
            unsigned ah[4][4], al[4][4], bh[4][2], bl[4][2];
            const int arow = wm + (lane & 15);
            const int acol = ks + (lane >> 4) * 8;
#pragma unroll
            for (int mt = 0; mt < 4; mt++) {
                ldm_x4(smem_u32(&Ah[arow + mt * 16][acol]),
                       ah[mt][0], ah[mt][1], ah[mt][2], ah[mt][3]);
                ldm_x4(smem_u32(&Al[arow + mt * 16][acol]),
                       al[mt][0], al[mt][1], al[mt][2], al[mt][3]);
            }
            const int brow = wn + (lane & 7);
            const int bcol = ks + ((lane >> 3) & 1) * 8;
#pragma unroll
            for (int nt = 0; nt < 4; nt++) {
                ldm_x2(smem_u32(&Bh[brow + nt * 8][bcol]), bh[nt][0], bh[nt][1]);
                ldm_x2(smem_u32(&Bl[brow + nt * 8][bcol]), bl[nt][0], bl[nt][1]);
            }
#pragma unroll
            for (int mt = 0; mt < 4; mt++)
#pragma unroll
                for (int nt = 0; nt < 4; nt++) {
                    mma16816(acc[mt][nt], ah[mt], bh[nt]);
                    mma16816(acc[mt][nt], ah[mt], bl[nt]);
                    mma16816(acc[mt][nt], al[mt], bh[nt]);
                }
        }
        __syncthreads();
    }

    const float scale = 0.125f;
#pragma unroll
    for (int mt = 0; mt < 4; mt++) {
        int mrow = m0 + wm + mt * 16 + (lane >> 2);
#pragma unroll
        for (int nt = 0; nt < 4; nt++) {
            int ncol = n0 + wn + nt * 8 + (lane & 3) * 2;
#pragma unroll
            for (int half = 0; half < 2; half++) {
                int m = mrow + half * 8;
                float2 v;
                v.x = acc[mt][nt][half * 2 + 0] * scale;
                v.y = acc[mt][nt][half * 2 + 1] * scale;
                *reinterpret_cast<float2*>(C + (size_t)m * SS + ncol) = v;
            }
        }
    }
}

// ---------------------------------------------------------------------------
// softmax: in-place over last dim (2048), one block per row, 256 threads
// ---------------------------------------------------------------------------
__global__ __launch_bounds__(256) void softmax_kernel(float* __restrict__ attn)
{
    const size_t row = blockIdx.x;
    float4* p4 = reinterpret_cast<float4*>(attn + row * SS);
    const int tid = threadIdx.x;

    float4 v0 = p4[tid];
    float4 v1 = p4[tid + 256];

    float mx = fmaxf(fmaxf(fmaxf(v0.x, v0.y), fmaxf(v0.z, v0.w)),
                     fmaxf(fmaxf(v1.x, v1.y), fmaxf(v1.z, v1.w)));

    __shared__ float redm[8];
    __shared__ float reds[8];
    const int lane = tid & 31, wrp = tid >> 5;

#pragma unroll
    for (int o = 16; o > 0; o >>= 1)
        mx = fmaxf(mx, __shfl_xor_sync(0xffffffffu, mx, o));
    if (lane == 0) redm[wrp] = mx;
    __syncthreads();
    mx = redm[0];
#pragma unroll
    for (int wq = 1; wq < 8; wq++) mx = fmaxf(mx, redm[wq]);

    float4 e0, e1;
    e0.x = __expf(v0.x - mx); e0.y = __expf(v0.y - mx);
    e0.z = __expf(v0.z - mx); e0.w = __expf(v0.w - mx);
    e1.x = __expf(v1.x - mx); e1.y = __expf(v1.y - mx);
    e1.z = __expf(v1.z - mx); e1.w = __expf(v1.w - mx);

    float sm = (e0.x + e0.y + e0.z + e0.w) + (e1.x + e1.y + e1.z + e1.w);
#pragma unroll
    for (int o = 16; o > 0; o >>= 1)
        sm += __shfl_xor_sync(0xffffffffu, sm, o);
    if (lane == 0) reds[wrp] = sm;
    __syncthreads();
    sm = reds[0];
#pragma unroll
    for (int wq = 1; wq < 8; wq++) sm += reds[wq];

    const float inv = 1.0f / sm;
    e0.x *= inv; e0.y *= inv; e0.z *= inv; e0.w *= inv;
    e1.x *= inv; e1.y *= inv; e1.z *= inv; e1.w *= inv;
    p4[tid] = e0;
    p4[tid + 256] = e1;
}

// ---------------------------------------------------------------------------
// AV (tensor cores): per (b,h) Z[2048,64] = P[2048,2048] @ V[2048,64]
// Block tile 128x64, K-tile 32. 8 warps, warp grid 4m x 2n (warp tile 32x32).
// V is [k][n] in global; transposed into smem to be K-contiguous.
// ---------------------------------------------------------------------------
__global__ __launch_bounds__(256) void av_kernel(const float* __restrict__ attn)
{
    __shared__ alignas(16) __nv_bfloat16 Ph[128][40];
    __shared__ alignas(16) __nv_bfloat16 Pl[128][40];
    __shared__ alignas(16) __nv_bfloat16 Vh[64][40];
    __shared__ alignas(16) __nv_bfloat16 Vl[64][40];

    const int bh = blockIdx.z;
    const int b = bh >> 4, h = bh & 15;
    const float* P = attn + (size_t)bh * SS * SS;
    const float* V = g_Vh + (size_t)bh * SS * HD;

    const int m0 = blockIdx.x * 128;
    const int tid = threadIdx.x;
    const int lane = tid & 31;
    const int w = tid >> 5;
    const int wm = (w >> 1) * 32;   // 0,32,64,96
    const int wn = (w & 1) * 32;    // 0,32

    float acc[2][4][4];
#pragma unroll
    for (int i = 0; i < 2; i++)
#pragma unroll
        for (int j = 0; j < 4; j++)
#pragma unroll
            for (int c = 0; c < 4; c++) acc[i][j][c] = 0.f;

    for (int k0 = 0; k0 < SS; k0 += 32) {
        // P tile 128x32
#pragma unroll
        for (int r = 0; r < 4; r++) {
            int idx = tid + r * 256;
            int row = idx >> 3;
            int kc = (idx & 7) * 4;
            float4 pv = *reinterpret_cast<const float4*>(
                P + (size_t)(m0 + row) * SS + k0 + kc);
            split_store4(&Ph[row][0], &Pl[row][0], kc, pv);
        }
        // V tile 32(k) x 64(n), transposed store
#pragma unroll
        for (int r = 0; r < 2; r++) {
            int idx = tid + r * 256;      // 0..511
            int krow = idx >> 4;          // 0..31
            int nc = (idx & 15) * 4;      // 0..60
            float4 vv = *reinterpret_cast<const float4*>(
                V + (size_t)(k0 + krow) * HD + nc);
            __nv_bfloat16 hh, ll;
            split2(vv.x, hh, ll); Vh[nc + 0][krow] = hh; Vl[nc + 0][krow] = ll;
            split2(vv.y, hh, ll); Vh[nc + 1][krow] = hh; Vl[nc + 1][krow] = ll;
            split2(vv.z, hh, ll); Vh[nc + 2][krow] = hh; Vl[nc + 2][krow] = ll;
            split2(vv.w, hh, ll); Vh[nc + 3][krow] = hh; Vl[nc + 3][krow] = ll;
        }
        __syncthreads();

#pragma unroll
        for (int ks = 0; ks < 32; ks += 16) {
            unsigned ah[2][4], al[2][4], bh2[4][2], bl2[4][2];
            const int arow = wm + (lane & 15);
            const int acol = ks + (lane >> 4) * 8;
#pragma unroll
            for (int mt = 0; mt < 2; mt++) {
                ldm_x4(smem_u32(&Ph[arow + mt * 16][acol]),
                       ah[mt][0], ah[mt][1], ah[mt][2], ah[mt][3]);
                ldm_x4(smem_u32(&Pl[arow + mt * 16][acol]),
                       al[mt][0], al[mt][1], al[mt][2], al[mt][3]);
            }
            const int brow = wn + (lane & 7);
            const int bcol = ks + ((lane >> 3) & 1) * 8;
#pragma unroll
            for (int nt = 0; nt < 4; nt++) {
                ldm_x2(smem_u32(&Vh[brow + nt * 8][bcol]), bh2[nt][0], bh2[nt][1]);
                ldm_x2(smem_u32(&Vl[brow + nt * 8][bcol]), bl2[nt][0], bl2[nt][1]);
            }
#pragma unroll
            for (int mt = 0; mt < 2; mt++)
#pragma unroll
                for (int nt = 0; nt < 4; nt++) {
                    mma16816(acc[mt][nt], ah[mt], bh2[nt]);
                    mma16816(acc[mt][nt], ah[mt], bl2[nt]);
                    mma16816(acc[mt][nt], al[mt], bh2[nt]);
                }
        }
        __syncthreads();
    }

#pragma unroll
    for (int mt = 0; mt < 2; mt++) {
        int mrow = m0 + wm + mt * 16 + (lane >> 2);
#pragma unroll
        for (int nt = 0; nt < 4; nt++) {
            int ncol = h * HD + wn + nt * 8 + (lane & 3) * 2;
#pragma unroll
            for (int half = 0; half < 2; half++) {
                int m = mrow + half * 8;
                float2 v;
                v.x = acc[mt][nt][half * 2 + 0];
                v.y = acc[mt][nt][half * 2 + 1];
                *reinterpret_cast<float2*>(
                    &g_Z[((size_t)b * SS + m) * DM + ncol]) = v;
            }
        }
    }
}

// ---------------------------------------------------------------------------
extern "C" void kernel_launch(void* const* d_in, const int* in_sizes, int n_in,
                              void* d_out, int out_size)
{
    const float* q   = (const float*)d_in[0];
    const float* k   = (const float*)d_in[1];
    const float* v   = (const float*)d_in[2];
    const float* w_q = (const float*)d_in[3];
    const float* b_q = (const float*)d_in[4];
    const float* w_k = (const float*)d_in[5];
    const float* b_k = (const float*)d_in[6];
    const float* w_v = (const float*)d_in[7];
    const float* b_v = (const float*)d_in[8];
    const float* w_o = (const float*)d_in[9];
    const float* b_o = (const float*)d_in[10];

    float* out = (float*)d_out;
    float* z_out = out;                    // [B,S,D]
    float* attn_out = out + Z_ELEMS;       // [B,H,S,S]

    dim3 gp(DM / 128, MROWS / 128);        // (8, 32)
    proj_kernel<0><<<gp, 256>>>(q, w_q, b_q, nullptr);
    proj_kernel<1><<<gp, 256>>>(k, w_k, b_k, nullptr);
    proj_kernel<2><<<gp, 256>>>(v, w_v, b_v, nullptr);

    scores_kernel<<<dim3(SS / 128, SS / 128, BB * NH), 256>>>(attn_out);
    softmax_kernel<<<BB * NH * SS, 256>>>(attn_out);
    av_kernel<<<dim3(SS / 128, 1, BB * NH), 256>>>(attn_out);

    proj_kernel<3><<<gp, 256>>>(nullptr, w_o, b_o, z_out);
}